// round 15
// baseline (speedup 1.0000x reference)
#include <cuda_runtime.h>
#include <cuda_fp16.h>
#include <cstdint>

#define N_ATOMS 50000
#define N_PAIRS 1600000
#define LN2F 0.6931471805599453f
#define CAP 96

__device__ float g_x[(size_t)N_ATOMS * 128];
__device__ float g_acc[(size_t)N_ATOMS * 128];
__device__ __half g_wh[(size_t)N_PAIRS * 128];   // cutoff-weighted filters (fp16 storage)
__device__ int   g_cnt[N_ATOMS];
__device__ int2  g_bucket[(size_t)N_ATOMS * CAP];

// ---------------------------------------------------------------------------
// helpers
// ---------------------------------------------------------------------------
__device__ __forceinline__ float fssp(float x) {
    if (x > 60.f) return x - LN2F;
    float t, l;
    asm("ex2.approx.f32 %0, %1;" : "=f"(t) : "f"(x * 1.4426950408889634f));
    asm("lg2.approx.f32 %0, %1;" : "=f"(l) : "f"(t + 1.0f));
    return 0.69314718055994531f * (l - 1.0f);
}
__device__ __forceinline__ void barh(int id) {
    asm volatile("bar.sync %0, 256;" :: "r"(id) : "memory");
}
__device__ __forceinline__ uint32_t packh2(float a, float b) {
    __half2 h = __floats2half2_rn(a, b);
    return *reinterpret_cast<uint32_t*>(&h);
}
__device__ __forceinline__ float2 unpackh2(uint32_t u) {
    __half2 h = *reinterpret_cast<__half2*>(&u);
    return __half22float2(h);
}
__device__ __forceinline__ void stcs_u2(void* p, uint2 v) {
    asm volatile("st.global.cs.v2.u32 [%0], {%1, %2};" :: "l"(p), "r"(v.x), "r"(v.y) : "memory");
}
__device__ __forceinline__ uint2 ldcs_u2(const void* p) {
    uint2 v;
    asm volatile("ld.global.cs.v2.u32 {%0, %1}, [%2];" : "=r"(v.x), "=r"(v.y) : "l"(p));
    return v;
}
__device__ __forceinline__ void mma16(float c[4], const uint32_t a[4], const uint32_t b[2]) {
    asm volatile(
        "mma.sync.aligned.m16n8k16.row.col.f32.f16.f16.f32 "
        "{%0,%1,%2,%3}, {%4,%5,%6,%7}, {%8,%9}, {%0,%1,%2,%3};\n"
        : "+f"(c[0]), "+f"(c[1]), "+f"(c[2]), "+f"(c[3])
        : "r"(a[0]), "r"(a[1]), "r"(a[2]), "r"(a[3]), "r"(b[0]), "r"(b[1]));
}

// ---------------------------------------------------------------------------
// fp16 fragment-major word indexing (m16n8k16) — validated rounds 12-14
// ---------------------------------------------------------------------------
__device__ __forceinline__ int aword(int row, int c, int kst) {
    int f4 = (((row >> 5) * kst + (c >> 4)) * 2 + ((row >> 4) & 1)) * 32
           + (row & 7) * 4 + (((c & 15) & 7) >> 1);
    return f4 * 4 + ((c & 15) >> 3) * 2 + ((row >> 3) & 1);
}
__device__ __forceinline__ int bword(int kk, int n, int kst) {
    int f4 = (n >> 6) * (kst * 128) + (kk >> 4) * 128 + (((n >> 3) & 7) >> 1) * 32
           + (n & 7) * 4 + (((kk & 15) & 7) >> 1);
    return f4 * 4 + ((n >> 3) & 1) * 2 + ((kk & 15) >> 3);
}

template <int KST>
__device__ __forceinline__ void gemmH(const float* __restrict__ Af,
                                      const float* __restrict__ Bf,
                                      float C[2][8][4], int htid) {
    const int lane = htid & 31, warp = htid >> 5;
    const float4* A4 = (const float4*)Af + (warp >> 1) * (KST * 64) + lane;
    const float4* B4 = (const float4*)Bf + (warp & 1) * (KST * 128) + lane;
#pragma unroll
    for (int k = 0; k < KST; ++k) {
        float4 fa0 = A4[k * 64];
        float4 fa1 = A4[k * 64 + 32];
        uint32_t a[2][4] = {
            {__float_as_uint(fa0.x), __float_as_uint(fa0.y), __float_as_uint(fa0.z), __float_as_uint(fa0.w)},
            {__float_as_uint(fa1.x), __float_as_uint(fa1.y), __float_as_uint(fa1.z), __float_as_uint(fa1.w)}};
        uint32_t b[8][2];
#pragma unroll
        for (int g = 0; g < 4; ++g) {
            float4 fb = B4[k * 128 + g * 32];
            b[2 * g][0] = __float_as_uint(fb.x);
            b[2 * g][1] = __float_as_uint(fb.y);
            b[2 * g + 1][0] = __float_as_uint(fb.z);
            b[2 * g + 1][1] = __float_as_uint(fb.w);
        }
#pragma unroll
        for (int i = 0; i < 2; ++i)
#pragma unroll
            for (int j = 0; j < 8; ++j) mma16(C[i][j], a[i], b[j]);
    }
}

// smem float offsets for k_pair
#define OFF_BF2  0        // W_f2 frags: 8192 f
#define OFF_BF1  8192     // W_f1 frags: 2048 f
#define OFF_BB1  10240
#define OFF_BB2  10368
#define OFF_UNI0 10496
#define UNI_W    8704     // union: A2 frags (8192 f) / w h2-rows [128][68]
#define A1_OFF   UNI_W    // A1 frags, separate: 2048 f
#define HALF_STRIDE (UNI_W + 2048 + 128)  // + A1 + scut = 10880
#define SMEM_PAIR_F (OFF_UNI0 + 2 * HALF_STRIDE)  // 32256 f = 129024 B

#define SMEM_ATOM_F (8192 + 8192 + 256)          // k_proj: 66560 B
#define SMEM_OUT_F  (8192 + 8192 + 8192 + 256)   // k_out: 99328 B

// ---------------------------------------------------------------------------
// bucketing
// ---------------------------------------------------------------------------
__global__ void k_czero() {
    int i = blockIdx.x * blockDim.x + threadIdx.x;
    if (i < N_ATOMS) g_cnt[i] = 0;
}
__global__ void k_bucket(const int* __restrict__ pidx) {
    int p = blockIdx.x * blockDim.x + threadIdx.x;
    if (p < N_PAIRS) {
        int i = __ldg(&pidx[p]);
        int j = __ldg(&pidx[N_PAIRS + p]);
        int slot = atomicAdd(&g_cnt[i], 1);
        if (slot < CAP) g_bucket[(size_t)i * CAP + slot] = make_int2(p, j);
    }
}

// ---------------------------------------------------------------------------
// x = atomic_embedding @ W_in -> g_x  (fp16 mma, 2 CTA/SM)
// ---------------------------------------------------------------------------
__global__ __launch_bounds__(256, 2) void k_proj(const float* __restrict__ emb,
                                                 const float* __restrict__ W_in) {
    extern __shared__ float smem[];
    float* Af = smem;
    float* Bf = smem + 8192;
    const int tid = threadIdx.x;
    const int r0 = blockIdx.x * 128;

    for (int t = tid; t < 128 * 64; t += 256) {
        int row = t >> 6, cp = t & 63;
        float2 v = make_float2(0.f, 0.f);
        if (r0 + row < N_ATOMS)
            v = *reinterpret_cast<const float2*>(&emb[(size_t)(r0 + row) * 128 + 2 * cp]);
        ((uint32_t*)Af)[aword(row, 2 * cp, 8)] = packh2(v.x, v.y);
    }
    for (int t = tid; t < 64 * 128; t += 256) {
        int kk = (t >> 7) * 2, n = t & 127;
        ((uint32_t*)Bf)[bword(kk, n, 8)] = packh2(W_in[kk * 128 + n], W_in[(kk + 1) * 128 + n]);
    }
    __syncthreads();

    float C[2][8][4] = {};
    gemmH<8>(Af, Bf, C, tid);

    const int lane = tid & 31, warp = tid >> 5;
    const int wm = (warp >> 1) * 32, wn = (warp & 1) * 64;
    const int gid = lane >> 2, tig = lane & 3;
#pragma unroll
    for (int i = 0; i < 2; ++i)
#pragma unroll
        for (int h = 0; h < 2; ++h) {
            int row = r0 + wm + i * 16 + gid + h * 8;
            if (row < N_ATOMS)
#pragma unroll
                for (int j = 0; j < 8; ++j) {
                    int col = wn + j * 8 + 2 * tig;
                    float2 v = make_float2(C[i][j][h * 2], C[i][j][h * 2 + 1]);
                    *reinterpret_cast<float2*>(&g_x[(size_t)row * 128 + col]) = v;
                }
        }
}

// ---------------------------------------------------------------------------
// Phase A: persistent filter-network GEMMs (fp16 mma); streaming fp16 w write.
// A1 tile separate from the A2/w union -> pads zeroed once, 4 barriers/tile.
// ---------------------------------------------------------------------------
__global__ __launch_bounds__(512, 1)
void k_pair(const float* __restrict__ f_ij, const float* __restrict__ cut,
            const float* __restrict__ W_f1, const float* __restrict__ b_f1,
            const float* __restrict__ W_f2, const float* __restrict__ b_f2,
            int tile_base, int tile_count) {
    extern __shared__ float smem[];
    const int tid = threadIdx.x;
    const int half = tid >> 8;
    const int htid = tid & 255;

    float* Bf2 = smem + OFF_BF2;
    float* Bf1 = smem + OFF_BF1;
    float* uni = smem + OFF_UNI0 + half * HALF_STRIDE;
    float* A1f = uni + A1_OFF;
    float* scut = A1f + 2048;
    uint32_t* uw = (uint32_t*)uni;
    uint32_t* a1w = (uint32_t*)A1f;

    for (int t = tid; t < 64 * 128; t += 512) {
        int kk = (t >> 7) * 2, n = t & 127;
        ((uint32_t*)Bf2)[bword(kk, n, 8)] =
            packh2(W_f2[kk * 128 + n], W_f2[(kk + 1) * 128 + n]);
    }
    for (int t = tid; t < 16 * 128; t += 512) {
        int kk = (t >> 7) * 2, n = t & 127;
        float v0 = (kk < 20) ? W_f1[kk * 128 + n] : 0.f;
        float v1 = (kk + 1 < 20) ? W_f1[(kk + 1) * 128 + n] : 0.f;
        ((uint32_t*)Bf1)[bword(kk, n, 2)] = packh2(v0, v1);
    }
    if (tid < 128) smem[OFF_BB1 + tid] = b_f1[tid];
    else if (tid < 256) smem[OFF_BB2 + tid - 128] = b_f2[tid - 128];
    // zero A1 pad columns once (c = 20..31)
    for (int t = htid; t < 128 * 6; t += 256) {
        int row = t / 6, c = 20 + 2 * (t % 6);
        a1w[aword(row, c, 2)] = 0u;
    }
    __syncthreads();

    const float* b1s = smem + OFF_BB1;
    const float* b2s = smem + OFF_BB2;
    const int bar = 1 + half;
    const int lane = htid & 31, warp = htid >> 5;
    const int wm = (warp >> 1) * 32, wn = (warp & 1) * 64;
    const int gid = lane >> 2, tig = lane & 3;

    const int end = tile_base + tile_count;
    const int step = (int)gridDim.x * 2;
    int tile = tile_base + (int)blockIdx.x * 2 + half;
    if (tile >= end) return;

    const int prow = htid >> 1;
    const int podd = htid & 1;
    const int pcol = podd * 10;
    float pf[10];
    float pcut = 0.f;
    {
        const float* src = f_ij + (size_t)(tile * 128 + prow) * 20 + pcol;
#pragma unroll
        for (int q = 0; q < 10; ++q) pf[q] = __ldcs(src + q);
        if (htid < 128) pcut = __ldcs(&cut[tile * 128 + htid]);
    }

    float4* A2v = (float4*)uni + (((warp >> 1) * 8 + (wn >> 4)) * 2) * 32 + lane;

    for (; tile < end; tile += step) {
        const int p0 = tile * 128;

        // S1: prefetched f_ij -> A1 fragment words (pads already zero)
#pragma unroll
        for (int q = 0; q < 5; ++q)
            a1w[aword(prow, pcol + q * 2, 2)] = packh2(pf[2 * q], pf[2 * q + 1]);
        if (htid < 128) scut[htid] = pcut;
        barh(bar);

        int nt = tile + step;
        if (nt < end) {
            const float* src = f_ij + (size_t)(nt * 128 + prow) * 20 + pcol;
#pragma unroll
            for (int q = 0; q < 10; ++q) pf[q] = __ldcs(src + q);
            if (htid < 128) pcut = __ldcs(&cut[nt * 128 + htid]);
        }

        // GEMM1 (K=32 incl pad -> 2 ksteps, fp16); A1 separate, no barrier after
        float C[2][8][4] = {};
        gemmH<2>(A1f, Bf1, C, htid);

        // S3: hidden = fp16(fssp(C+b1)) -> A2 fragments (union; safe: all warps
        // passed last tile's end-of-tile barrier before this tile's bar1)
#pragma unroll
        for (int i = 0; i < 2; ++i) {
#pragma unroll
            for (int q = 0; q < 4; ++q) {
                int c0 = wn + q * 16 + 2 * tig;
                int c1 = c0 + 8;
                float4 o;
                o.x = __uint_as_float(packh2(fssp(C[i][2 * q][0] + b1s[c0]),
                                             fssp(C[i][2 * q][1] + b1s[c0 + 1])));
                o.y = __uint_as_float(packh2(fssp(C[i][2 * q][2] + b1s[c0]),
                                             fssp(C[i][2 * q][3] + b1s[c0 + 1])));
                o.z = __uint_as_float(packh2(fssp(C[i][2 * q + 1][0] + b1s[c1]),
                                             fssp(C[i][2 * q + 1][1] + b1s[c1 + 1])));
                o.w = __uint_as_float(packh2(fssp(C[i][2 * q + 1][2] + b1s[c1]),
                                             fssp(C[i][2 * q + 1][3] + b1s[c1 + 1])));
                A2v[(q * 2 + i) * 32] = o;
            }
        }
        barh(bar);

        // GEMM2 (K=128 -> 8 ksteps, fp16)
        float C2[2][8][4] = {};
        gemmH<8>(uni, Bf2, C2, htid);
        barh(bar);  // all A2 reads done before w-stage overwrites union

        // stage w = fp16((C2+b2)*cut) as h2 words, rows stride 68
#pragma unroll
        for (int i = 0; i < 2; ++i)
#pragma unroll
            for (int h = 0; h < 2; ++h) {
                int r = wm + i * 16 + gid + h * 8;
                float ct = scut[r];
#pragma unroll
                for (int j = 0; j < 8; ++j) {
                    int c2 = (wn >> 1) + j * 4 + tig;
                    uw[r * 68 + c2] = packh2((C2[i][j][h * 2] + b2s[2 * c2]) * ct,
                                             (C2[i][j][h * 2 + 1] + b2s[2 * c2 + 1]) * ct);
                }
            }
        barh(bar);

        // coalesced streaming write-out: warp = full 256B rows
#pragma unroll
        for (int rr = 0; rr < 16; ++rr) {
            int row = warp * 16 + rr;
            uint2 v = make_uint2(uw[row * 68 + lane * 2], uw[row * 68 + lane * 2 + 1]);
            stcs_u2((uint2*)(g_wh + (size_t)(p0 + row) * 128) + lane, v);
        }
        barh(bar);  // uw reads done before next tile's S3 overwrite
    }
}

// ---------------------------------------------------------------------------
// Phase B: one warp per atom sums w[p] * x[j]; int4 bucket fetch, streaming w
// ---------------------------------------------------------------------------
__global__ void k_gather() {
    int atom = ((int)blockIdx.x * 256 + (int)threadIdx.x) >> 5;
    int lane = threadIdx.x & 31;
    if (atom >= N_ATOMS) return;
    int cnt = __ldg(&g_cnt[atom]);
    if (cnt > CAP) cnt = CAP;
    const int2* bucket = g_bucket + (size_t)atom * CAP;
    float4 acc = make_float4(0.f, 0.f, 0.f, 0.f);

    int t = 0;
    for (; t + 2 <= cnt; t += 2) {
        int4 e = __ldg((const int4*)(bucket + t));
        uint2 w0 = ldcs_u2((const uint2*)(g_wh + (size_t)e.x * 128) + lane);
        float4 x0 = __ldg((const float4*)(g_x + (size_t)e.y * 128) + lane);
        uint2 w1 = ldcs_u2((const uint2*)(g_wh + (size_t)e.z * 128) + lane);
        float4 x1 = __ldg((const float4*)(g_x + (size_t)e.w * 128) + lane);
        float2 a0 = unpackh2(w0.x), b0 = unpackh2(w0.y);
        float2 a1 = unpackh2(w1.x), b1 = unpackh2(w1.y);
        acc.x += a0.x * x0.x; acc.y += a0.y * x0.y;
        acc.z += b0.x * x0.z; acc.w += b0.y * x0.w;
        acc.x += a1.x * x1.x; acc.y += a1.y * x1.y;
        acc.z += b1.x * x1.z; acc.w += b1.y * x1.w;
    }
    if (t < cnt) {
        int2 e = __ldg(&bucket[t]);
        uint2 w = ldcs_u2((const uint2*)(g_wh + (size_t)e.x * 128) + lane);
        float4 x = __ldg((const float4*)(g_x + (size_t)e.y * 128) + lane);
        float2 a = unpackh2(w.x), b = unpackh2(w.y);
        acc.x += a.x * x.x; acc.y += a.y * x.y;
        acc.z += b.x * x.z; acc.w += b.y * x.w;
    }
    *((float4*)(g_acc + (size_t)atom * 128) + lane) = acc;
}

// ---------------------------------------------------------------------------
// Output MLP (fp16 mma, 2 CTA/SM, both weight sets preloaded)
// ---------------------------------------------------------------------------
__global__ __launch_bounds__(256, 2) void k_out(const float* __restrict__ W_o1,
                                                const float* __restrict__ b_o1,
                                                const float* __restrict__ W_o2,
                                                const float* __restrict__ b_o2,
                                                float* __restrict__ out) {
    extern __shared__ float smem[];
    float* Af  = smem;
    float* Bf1w = smem + 8192;
    float* Bf2w = smem + 16384;
    float* sb1 = smem + 24576;
    float* sb2 = smem + 24704;
    const int tid = threadIdx.x;
    const int r0 = blockIdx.x * 128;

    for (int t = tid; t < 128 * 64; t += 256) {
        int row = t >> 6, cp = t & 63;
        float2 v = make_float2(0.f, 0.f);
        if (r0 + row < N_ATOMS)
            v = *reinterpret_cast<const float2*>(&g_acc[(size_t)(r0 + row) * 128 + 2 * cp]);
        ((uint32_t*)Af)[aword(row, 2 * cp, 8)] = packh2(v.x, v.y);
    }
    for (int t = tid; t < 64 * 128; t += 256) {
        int kk = (t >> 7) * 2, n = t & 127;
        ((uint32_t*)Bf1w)[bword(kk, n, 8)] = packh2(W_o1[kk * 128 + n], W_o1[(kk + 1) * 128 + n]);
        ((uint32_t*)Bf2w)[bword(kk, n, 8)] = packh2(W_o2[kk * 128 + n], W_o2[(kk + 1) * 128 + n]);
    }
    if (tid < 128) sb1[tid] = b_o1[tid];
    else sb2[tid - 128] = b_o2[tid - 128];
    __syncthreads();

    float C[2][8][4] = {};
    gemmH<8>(Af, Bf1w, C, tid);
    __syncthreads();  // all Af reads done before repack

    const int lane = tid & 31, warp = tid >> 5;
    const int wm = (warp >> 1) * 32, wn = (warp & 1) * 64;
    const int gid = lane >> 2, tig = lane & 3;

    float4* A2v = (float4*)Af + (((warp >> 1) * 8 + (wn >> 4)) * 2) * 32 + lane;
#pragma unroll
    for (int i = 0; i < 2; ++i) {
#pragma unroll
        for (int q = 0; q < 4; ++q) {
            int c0 = wn + q * 16 + 2 * tig;
            int c1 = c0 + 8;
            float4 o;
            o.x = __uint_as_float(packh2(fssp(C[i][2 * q][0] + sb1[c0]),
                                         fssp(C[i][2 * q][1] + sb1[c0 + 1])));
            o.y = __uint_as_float(packh2(fssp(C[i][2 * q][2] + sb1[c0]),
                                         fssp(C[i][2 * q][3] + sb1[c0 + 1])));
            o.z = __uint_as_float(packh2(fssp(C[i][2 * q + 1][0] + sb1[c1]),
                                         fssp(C[i][2 * q + 1][1] + sb1[c1 + 1])));
            o.w = __uint_as_float(packh2(fssp(C[i][2 * q + 1][2] + sb1[c1]),
                                         fssp(C[i][2 * q + 1][3] + sb1[c1 + 1])));
            A2v[(q * 2 + i) * 32] = o;
        }
    }
    __syncthreads();

    float C2[2][8][4] = {};
    gemmH<8>(Af, Bf2w, C2, tid);

#pragma unroll
    for (int i = 0; i < 2; ++i)
#pragma unroll
        for (int h = 0; h < 2; ++h) {
            int row = r0 + wm + i * 16 + gid + h * 8;
            if (row < N_ATOMS)
#pragma unroll
                for (int j = 0; j < 8; ++j) {
                    int col = wn + j * 8 + 2 * tig;
                    float2 v = make_float2(C2[i][j][h * 2] + sb2[col],
                                           C2[i][j][h * 2 + 1] + sb2[col + 1]);
                    *reinterpret_cast<float2*>(&out[(size_t)row * 128 + col]) = v;
                }
        }
}

extern "C" void kernel_launch(void* const* d_in, const int* in_sizes, int n_in,
                              void* d_out, int out_size) {
    const float* emb  = (const float*)d_in[0];
    const int*   pidx = (const int*)d_in[1];
    const float* fij  = (const float*)d_in[2];
    const float* cut  = (const float*)d_in[3];
    const float* W_in = (const float*)d_in[4];
    const float* W_f1 = (const float*)d_in[5];
    const float* b_f1 = (const float*)d_in[6];
    const float* W_f2 = (const float*)d_in[7];
    const float* b_f2 = (const float*)d_in[8];
    const float* W_o1 = (const float*)d_in[9];
    const float* b_o1 = (const float*)d_in[10];
    const float* W_o2 = (const float*)d_in[11];
    const float* b_o2 = (const float*)d_in[12];
    float* out = (float*)d_out;

    const int smemPair = SMEM_PAIR_F * 4;   // 129024 B
    const int smemAtom = SMEM_ATOM_F * 4;   // 66560 B
    const int smemOut  = SMEM_OUT_F * 4;    // 99328 B

    cudaFuncSetAttribute(k_pair, cudaFuncAttributeMaxDynamicSharedMemorySize, smemPair);
    cudaFuncSetAttribute(k_proj, cudaFuncAttributeMaxDynamicSharedMemorySize, smemAtom);
    cudaFuncSetAttribute(k_out,  cudaFuncAttributeMaxDynamicSharedMemorySize, smemOut);

    const int NT = N_PAIRS / 128;  // 12500
    k_czero<<<(N_ATOMS + 255) / 256, 256>>>();
    k_bucket<<<(N_PAIRS + 255) / 256, 256>>>(pidx);
    k_proj<<<(N_ATOMS + 127) / 128, 256, smemAtom>>>(emb, W_in);
    k_pair<<<148, 512, smemPair>>>(fij, cut, W_f1, b_f1, W_f2, b_f2, 0, NT / 2);
    k_pair<<<148, 512, smemPair>>>(fij, cut, W_f1, b_f1, W_f2, b_f2, NT / 2, NT - NT / 2);
    k_gather<<<(N_ATOMS * 32 + 255) / 256, 256>>>();
    k_out<<<(N_ATOMS + 127) / 128, 256, smemOut>>>(W_o1, b_o1, W_o2, b_o2, out);
}

// round 16
// speedup vs baseline: 1.0502x; 1.0502x over previous
#include <cuda_runtime.h>
#include <cuda_fp16.h>
#include <cstdint>

#define N_ATOMS 50000
#define N_PAIRS 1600000
#define LN2F 0.6931471805599453f
#define CAP 96

__device__ float g_x[(size_t)N_ATOMS * 128];
__device__ float g_acc[(size_t)N_ATOMS * 128];
__device__ __half g_wh[(size_t)N_PAIRS * 128];   // cutoff-weighted filters (fp16 storage)
__device__ int   g_cnt[N_ATOMS];
__device__ int2  g_bucket[(size_t)N_ATOMS * CAP];

// ---------------------------------------------------------------------------
// helpers
// ---------------------------------------------------------------------------
__device__ __forceinline__ float fssp(float x) {
    if (x > 60.f) return x - LN2F;
    float t, l;
    asm("ex2.approx.f32 %0, %1;" : "=f"(t) : "f"(x * 1.4426950408889634f));
    asm("lg2.approx.f32 %0, %1;" : "=f"(l) : "f"(t + 1.0f));
    return 0.69314718055994531f * (l - 1.0f);
}
__device__ __forceinline__ void barh(int id) {
    asm volatile("bar.sync %0, 256;" :: "r"(id) : "memory");
}
__device__ __forceinline__ uint32_t packh2(float a, float b) {
    __half2 h = __floats2half2_rn(a, b);
    return *reinterpret_cast<uint32_t*>(&h);
}
__device__ __forceinline__ float2 unpackh2(uint32_t u) {
    __half2 h = *reinterpret_cast<__half2*>(&u);
    return __half22float2(h);
}
__device__ __forceinline__ void stcs_u2(void* p, uint2 v) {
    asm volatile("st.global.cs.v2.u32 [%0], {%1, %2};" :: "l"(p), "r"(v.x), "r"(v.y) : "memory");
}
__device__ __forceinline__ uint2 ldcs_u2(const void* p) {
    uint2 v;
    asm volatile("ld.global.cs.v2.u32 {%0, %1}, [%2];" : "=r"(v.x), "=r"(v.y) : "l"(p));
    return v;
}
__device__ __forceinline__ void mma16(float c[4], const uint32_t a[4], const uint32_t b[2]) {
    asm volatile(
        "mma.sync.aligned.m16n8k16.row.col.f32.f16.f16.f32 "
        "{%0,%1,%2,%3}, {%4,%5,%6,%7}, {%8,%9}, {%0,%1,%2,%3};\n"
        : "+f"(c[0]), "+f"(c[1]), "+f"(c[2]), "+f"(c[3])
        : "r"(a[0]), "r"(a[1]), "r"(a[2]), "r"(a[3]), "r"(b[0]), "r"(b[1]));
}

// ---------------------------------------------------------------------------
// fp16 fragment-major word indexing (m16n8k16) — validated rounds 12-15
// ---------------------------------------------------------------------------
__device__ __forceinline__ int aword(int row, int c, int kst) {
    int f4 = (((row >> 5) * kst + (c >> 4)) * 2 + ((row >> 4) & 1)) * 32
           + (row & 7) * 4 + (((c & 15) & 7) >> 1);
    return f4 * 4 + ((c & 15) >> 3) * 2 + ((row >> 3) & 1);
}
__device__ __forceinline__ int bword(int kk, int n, int kst) {
    int f4 = (n >> 6) * (kst * 128) + (kk >> 4) * 128 + (((n >> 3) & 7) >> 1) * 32
           + (n & 7) * 4 + (((kk & 15) & 7) >> 1);
    return f4 * 4 + ((n >> 3) & 1) * 2 + ((kk & 15) >> 3);
}

template <int KST>
__device__ __forceinline__ void gemmH(const float* __restrict__ Af,
                                      const float* __restrict__ Bf,
                                      float C[2][8][4], int htid) {
    const int lane = htid & 31, warp = htid >> 5;
    const float4* A4 = (const float4*)Af + (warp >> 1) * (KST * 64) + lane;
    const float4* B4 = (const float4*)Bf + (warp & 1) * (KST * 128) + lane;
#pragma unroll
    for (int k = 0; k < KST; ++k) {
        float4 fa0 = A4[k * 64];
        float4 fa1 = A4[k * 64 + 32];
        uint32_t a[2][4] = {
            {__float_as_uint(fa0.x), __float_as_uint(fa0.y), __float_as_uint(fa0.z), __float_as_uint(fa0.w)},
            {__float_as_uint(fa1.x), __float_as_uint(fa1.y), __float_as_uint(fa1.z), __float_as_uint(fa1.w)}};
        uint32_t b[8][2];
#pragma unroll
        for (int g = 0; g < 4; ++g) {
            float4 fb = B4[k * 128 + g * 32];
            b[2 * g][0] = __float_as_uint(fb.x);
            b[2 * g][1] = __float_as_uint(fb.y);
            b[2 * g + 1][0] = __float_as_uint(fb.z);
            b[2 * g + 1][1] = __float_as_uint(fb.w);
        }
#pragma unroll
        for (int i = 0; i < 2; ++i)
#pragma unroll
            for (int j = 0; j < 8; ++j) mma16(C[i][j], a[i], b[j]);
    }
}

// smem float offsets for k_pair
#define OFF_BF2  0
#define OFF_BF1  8192
#define OFF_BB1  10240
#define OFF_BB2  10368
#define OFF_UNI0 10496
#define UNI_W    8704
#define A1_OFF   UNI_W
#define HALF_STRIDE (UNI_W + 2048 + 128)
#define SMEM_PAIR_F (OFF_UNI0 + 2 * HALF_STRIDE)  // 129024 B

#define SMEM_ATOM_F (8192 + 8192 + 256)           // k_proj: 66560 B
#define SMEM_OUT_F  (8192 + 8192 + 8192 + 256)    // k_out:  99328 B

// ---------------------------------------------------------------------------
// bucketing
// ---------------------------------------------------------------------------
__global__ void k_czero() {
    int i = blockIdx.x * blockDim.x + threadIdx.x;
    if (i < N_ATOMS) g_cnt[i] = 0;
}
__global__ void k_bucket(const int* __restrict__ pidx) {
    int p = blockIdx.x * blockDim.x + threadIdx.x;
    if (p < N_PAIRS) {
        int i = __ldg(&pidx[p]);
        int j = __ldg(&pidx[N_PAIRS + p]);
        int slot = atomicAdd(&g_cnt[i], 1);
        if (slot < CAP) g_bucket[(size_t)i * CAP + slot] = make_int2(p, j);
    }
}

// ---------------------------------------------------------------------------
// x = atomic_embedding @ W_in -> g_x  (fp16 mma, 2 CTA/SM)
// ---------------------------------------------------------------------------
__global__ __launch_bounds__(256, 2) void k_proj(const float* __restrict__ emb,
                                                 const float* __restrict__ W_in) {
    extern __shared__ float smem[];
    float* Af = smem;
    float* Bf = smem + 8192;
    const int tid = threadIdx.x;
    const int r0 = blockIdx.x * 128;

    for (int t = tid; t < 128 * 64; t += 256) {
        int row = t >> 6, cp = t & 63;
        float2 v = make_float2(0.f, 0.f);
        if (r0 + row < N_ATOMS)
            v = *reinterpret_cast<const float2*>(&emb[(size_t)(r0 + row) * 128 + 2 * cp]);
        ((uint32_t*)Af)[aword(row, 2 * cp, 8)] = packh2(v.x, v.y);
    }
    for (int t = tid; t < 64 * 128; t += 256) {
        int kk = (t >> 7) * 2, n = t & 127;
        ((uint32_t*)Bf)[bword(kk, n, 8)] = packh2(W_in[kk * 128 + n], W_in[(kk + 1) * 128 + n]);
    }
    __syncthreads();

    float C[2][8][4] = {};
    gemmH<8>(Af, Bf, C, tid);

    const int lane = tid & 31, warp = tid >> 5;
    const int wm = (warp >> 1) * 32, wn = (warp & 1) * 64;
    const int gid = lane >> 2, tig = lane & 3;
#pragma unroll
    for (int i = 0; i < 2; ++i)
#pragma unroll
        for (int h = 0; h < 2; ++h) {
            int row = r0 + wm + i * 16 + gid + h * 8;
            if (row < N_ATOMS)
#pragma unroll
                for (int j = 0; j < 8; ++j) {
                    int col = wn + j * 8 + 2 * tig;
                    float2 v = make_float2(C[i][j][h * 2], C[i][j][h * 2 + 1]);
                    *reinterpret_cast<float2*>(&g_x[(size_t)row * 128 + col]) = v;
                }
        }
}

// ---------------------------------------------------------------------------
// Phase A: persistent filter-network GEMMs (fp16 mma); streaming fp16 w write.
// ---------------------------------------------------------------------------
__global__ __launch_bounds__(512, 1)
void k_pair(const float* __restrict__ f_ij, const float* __restrict__ cut,
            const float* __restrict__ W_f1, const float* __restrict__ b_f1,
            const float* __restrict__ W_f2, const float* __restrict__ b_f2,
            int tile_base, int tile_count) {
    extern __shared__ float smem[];
    const int tid = threadIdx.x;
    const int half = tid >> 8;
    const int htid = tid & 255;

    float* Bf2 = smem + OFF_BF2;
    float* Bf1 = smem + OFF_BF1;
    float* uni = smem + OFF_UNI0 + half * HALF_STRIDE;
    float* A1f = uni + A1_OFF;
    float* scut = A1f + 2048;
    uint32_t* uw = (uint32_t*)uni;
    uint32_t* a1w = (uint32_t*)A1f;

    for (int t = tid; t < 64 * 128; t += 512) {
        int kk = (t >> 7) * 2, n = t & 127;
        ((uint32_t*)Bf2)[bword(kk, n, 8)] =
            packh2(W_f2[kk * 128 + n], W_f2[(kk + 1) * 128 + n]);
    }
    for (int t = tid; t < 16 * 128; t += 512) {
        int kk = (t >> 7) * 2, n = t & 127;
        float v0 = (kk < 20) ? W_f1[kk * 128 + n] : 0.f;
        float v1 = (kk + 1 < 20) ? W_f1[(kk + 1) * 128 + n] : 0.f;
        ((uint32_t*)Bf1)[bword(kk, n, 2)] = packh2(v0, v1);
    }
    if (tid < 128) smem[OFF_BB1 + tid] = b_f1[tid];
    else if (tid < 256) smem[OFF_BB2 + tid - 128] = b_f2[tid - 128];
    for (int t = htid; t < 128 * 6; t += 256) {
        int row = t / 6, c = 20 + 2 * (t % 6);
        a1w[aword(row, c, 2)] = 0u;
    }
    __syncthreads();

    const float* b1s = smem + OFF_BB1;
    const float* b2s = smem + OFF_BB2;
    const int bar = 1 + half;
    const int lane = htid & 31, warp = htid >> 5;
    const int wm = (warp >> 1) * 32, wn = (warp & 1) * 64;
    const int gid = lane >> 2, tig = lane & 3;

    const int end = tile_base + tile_count;
    const int step = (int)gridDim.x * 2;
    int tile = tile_base + (int)blockIdx.x * 2 + half;
    if (tile >= end) return;

    const int prow = htid >> 1;
    const int podd = htid & 1;
    const int pcol = podd * 10;
    float pf[10];
    float pcut = 0.f;
    {
        const float* src = f_ij + (size_t)(tile * 128 + prow) * 20 + pcol;
#pragma unroll
        for (int q = 0; q < 10; ++q) pf[q] = __ldcs(src + q);
        if (htid < 128) pcut = __ldcs(&cut[tile * 128 + htid]);
    }

    float4* A2v = (float4*)uni + (((warp >> 1) * 8 + (wn >> 4)) * 2) * 32 + lane;

    for (; tile < end; tile += step) {
        const int p0 = tile * 128;

        // S1: prefetched f_ij -> A1 fragment words (pads already zero)
#pragma unroll
        for (int q = 0; q < 5; ++q)
            a1w[aword(prow, pcol + q * 2, 2)] = packh2(pf[2 * q], pf[2 * q + 1]);
        if (htid < 128) scut[htid] = pcut;
        barh(bar);

        int nt = tile + step;
        if (nt < end) {
            const float* src = f_ij + (size_t)(nt * 128 + prow) * 20 + pcol;
#pragma unroll
            for (int q = 0; q < 10; ++q) pf[q] = __ldcs(src + q);
            if (htid < 128) pcut = __ldcs(&cut[nt * 128 + htid]);
        }

        // GEMM1 (K=32 incl pad -> 2 ksteps, fp16)
        float C[2][8][4] = {};
        gemmH<2>(A1f, Bf1, C, htid);

        // S3: hidden = fp16(fssp(C+b1)) -> A2 fragments
#pragma unroll
        for (int i = 0; i < 2; ++i) {
#pragma unroll
            for (int q = 0; q < 4; ++q) {
                int c0 = wn + q * 16 + 2 * tig;
                int c1 = c0 + 8;
                float4 o;
                o.x = __uint_as_float(packh2(fssp(C[i][2 * q][0] + b1s[c0]),
                                             fssp(C[i][2 * q][1] + b1s[c0 + 1])));
                o.y = __uint_as_float(packh2(fssp(C[i][2 * q][2] + b1s[c0]),
                                             fssp(C[i][2 * q][3] + b1s[c0 + 1])));
                o.z = __uint_as_float(packh2(fssp(C[i][2 * q + 1][0] + b1s[c1]),
                                             fssp(C[i][2 * q + 1][1] + b1s[c1 + 1])));
                o.w = __uint_as_float(packh2(fssp(C[i][2 * q + 1][2] + b1s[c1]),
                                             fssp(C[i][2 * q + 1][3] + b1s[c1 + 1])));
                A2v[(q * 2 + i) * 32] = o;
            }
        }
        barh(bar);

        // GEMM2 (K=128 -> 8 ksteps, fp16)
        float C2[2][8][4] = {};
        gemmH<8>(uni, Bf2, C2, htid);
        barh(bar);

        // stage w = fp16((C2+b2)*cut) as h2 words, rows stride 68
#pragma unroll
        for (int i = 0; i < 2; ++i)
#pragma unroll
            for (int h = 0; h < 2; ++h) {
                int r = wm + i * 16 + gid + h * 8;
                float ct = scut[r];
#pragma unroll
                for (int j = 0; j < 8; ++j) {
                    int c2 = (wn >> 1) + j * 4 + tig;
                    uw[r * 68 + c2] = packh2((C2[i][j][h * 2] + b2s[2 * c2]) * ct,
                                             (C2[i][j][h * 2 + 1] + b2s[2 * c2 + 1]) * ct);
                }
            }
        barh(bar);

        // coalesced streaming write-out: warp = full 256B rows
#pragma unroll
        for (int rr = 0; rr < 16; ++rr) {
            int row = warp * 16 + rr;
            uint2 v = make_uint2(uw[row * 68 + lane * 2], uw[row * 68 + lane * 2 + 1]);
            stcs_u2((uint2*)(g_wh + (size_t)(p0 + row) * 128) + lane, v);
        }
        barh(bar);
    }
}

// ---------------------------------------------------------------------------
// Phase B: one warp per atom sums w[p] * x[j]
// ---------------------------------------------------------------------------
__global__ void k_gather() {
    int atom = ((int)blockIdx.x * 256 + (int)threadIdx.x) >> 5;
    int lane = threadIdx.x & 31;
    if (atom >= N_ATOMS) return;
    int cnt = __ldg(&g_cnt[atom]);
    if (cnt > CAP) cnt = CAP;
    const int2* bucket = g_bucket + (size_t)atom * CAP;
    float4 acc = make_float4(0.f, 0.f, 0.f, 0.f);

    int t = 0;
    for (; t + 2 <= cnt; t += 2) {
        int4 e = __ldg((const int4*)(bucket + t));
        uint2 w0 = ldcs_u2((const uint2*)(g_wh + (size_t)e.x * 128) + lane);
        float4 x0 = __ldg((const float4*)(g_x + (size_t)e.y * 128) + lane);
        uint2 w1 = ldcs_u2((const uint2*)(g_wh + (size_t)e.z * 128) + lane);
        float4 x1 = __ldg((const float4*)(g_x + (size_t)e.w * 128) + lane);
        float2 a0 = unpackh2(w0.x), b0 = unpackh2(w0.y);
        float2 a1 = unpackh2(w1.x), b1 = unpackh2(w1.y);
        acc.x += a0.x * x0.x; acc.y += a0.y * x0.y;
        acc.z += b0.x * x0.z; acc.w += b0.y * x0.w;
        acc.x += a1.x * x1.x; acc.y += a1.y * x1.y;
        acc.z += b1.x * x1.z; acc.w += b1.y * x1.w;
    }
    if (t < cnt) {
        int2 e = __ldg(&bucket[t]);
        uint2 w = ldcs_u2((const uint2*)(g_wh + (size_t)e.x * 128) + lane);
        float4 x = __ldg((const float4*)(g_x + (size_t)e.y * 128) + lane);
        float2 a = unpackh2(w.x), b = unpackh2(w.y);
        acc.x += a.x * x.x; acc.y += a.y * x.y;
        acc.z += b.x * x.z; acc.w += b.y * x.w;
    }
    *((float4*)(g_acc + (size_t)atom * 128) + lane) = acc;
}

// ---------------------------------------------------------------------------
// Output MLP (fp16 mma, 2 CTA/SM, both weight sets preloaded)
// ---------------------------------------------------------------------------
__global__ __launch_bounds__(256, 2) void k_out(const float* __restrict__ W_o1,
                                                const float* __restrict__ b_o1,
                                                const float* __restrict__ W_o2,
                                                const float* __restrict__ b_o2,
                                                float* __restrict__ out) {
    extern __shared__ float smem[];
    float* Af   = smem;
    float* Bf1w = smem + 8192;
    float* Bf2w = smem + 16384;
    float* sb1  = smem + 24576;
    float* sb2  = smem + 24704;
    const int tid = threadIdx.x;
    const int r0 = blockIdx.x * 128;

    for (int t = tid; t < 128 * 64; t += 256) {
        int row = t >> 6, cp = t & 63;
        float2 v = make_float2(0.f, 0.f);
        if (r0 + row < N_ATOMS)
            v = *reinterpret_cast<const float2*>(&g_acc[(size_t)(r0 + row) * 128 + 2 * cp]);
        ((uint32_t*)Af)[aword(row, 2 * cp, 8)] = packh2(v.x, v.y);
    }
    for (int t = tid; t < 64 * 128; t += 256) {
        int kk = (t >> 7) * 2, n = t & 127;
        ((uint32_t*)Bf1w)[bword(kk, n, 8)] = packh2(W_o1[kk * 128 + n], W_o1[(kk + 1) * 128 + n]);
        ((uint32_t*)Bf2w)[bword(kk, n, 8)] = packh2(W_o2[kk * 128 + n], W_o2[(kk + 1) * 128 + n]);
    }
    if (tid < 128) sb1[tid] = b_o1[tid];
    else sb2[tid - 128] = b_o2[tid - 128];
    __syncthreads();

    float C[2][8][4] = {};
    gemmH<8>(Af, Bf1w, C, tid);
    __syncthreads();

    const int lane = tid & 31, warp = tid >> 5;
    const int wm = (warp >> 1) * 32, wn = (warp & 1) * 64;
    const int gid = lane >> 2, tig = lane & 3;

    float4* A2v = (float4*)Af + (((warp >> 1) * 8 + (wn >> 4)) * 2) * 32 + lane;
#pragma unroll
    for (int i = 0; i < 2; ++i) {
#pragma unroll
        for (int q = 0; q < 4; ++q) {
            int c0 = wn + q * 16 + 2 * tig;
            int c1 = c0 + 8;
            float4 o;
            o.x = __uint_as_float(packh2(fssp(C[i][2 * q][0] + sb1[c0]),
                                         fssp(C[i][2 * q][1] + sb1[c0 + 1])));
            o.y = __uint_as_float(packh2(fssp(C[i][2 * q][2] + sb1[c0]),
                                         fssp(C[i][2 * q][3] + sb1[c0 + 1])));
            o.z = __uint_as_float(packh2(fssp(C[i][2 * q + 1][0] + sb1[c1]),
                                         fssp(C[i][2 * q + 1][1] + sb1[c1 + 1])));
            o.w = __uint_as_float(packh2(fssp(C[i][2 * q + 1][2] + sb1[c1]),
                                         fssp(C[i][2 * q + 1][3] + sb1[c1 + 1])));
            A2v[(q * 2 + i) * 32] = o;
        }
    }
    __syncthreads();

    float C2[2][8][4] = {};
    gemmH<8>(Af, Bf2w, C2, tid);

#pragma unroll
    for (int i = 0; i < 2; ++i)
#pragma unroll
        for (int h = 0; h < 2; ++h) {
            int row = r0 + wm + i * 16 + gid + h * 8;
            if (row < N_ATOMS)
#pragma unroll
                for (int j = 0; j < 8; ++j) {
                    int col = wn + j * 8 + 2 * tig;
                    float2 v = make_float2(C2[i][j][h * 2] + sb2[col],
                                           C2[i][j][h * 2 + 1] + sb2[col + 1]);
                    *reinterpret_cast<float2*>(&out[(size_t)row * 128 + col]) = v;
                }
        }
}

// ---------------------------------------------------------------------------
// Launch: fork prologue (czero/bucket/proj) onto a side stream, overlapped
// with the k_pair chain; join before k_gather. Capture-legal fork/join.
// ---------------------------------------------------------------------------
extern "C" void kernel_launch(void* const* d_in, const int* in_sizes, int n_in,
                              void* d_out, int out_size) {
    const float* emb  = (const float*)d_in[0];
    const int*   pidx = (const int*)d_in[1];
    const float* fij  = (const float*)d_in[2];
    const float* cut  = (const float*)d_in[3];
    const float* W_in = (const float*)d_in[4];
    const float* W_f1 = (const float*)d_in[5];
    const float* b_f1 = (const float*)d_in[6];
    const float* W_f2 = (const float*)d_in[7];
    const float* b_f2 = (const float*)d_in[8];
    const float* W_o1 = (const float*)d_in[9];
    const float* b_o1 = (const float*)d_in[10];
    const float* W_o2 = (const float*)d_in[11];
    const float* b_o2 = (const float*)d_in[12];
    float* out = (float*)d_out;

    const int smemPair = SMEM_PAIR_F * 4;   // 129024 B
    const int smemAtom = SMEM_ATOM_F * 4;   // 66560 B
    const int smemOut  = SMEM_OUT_F * 4;    // 99328 B

    static bool inited = false;
    static cudaStream_t s2;
    if (!inited) {
        cudaStreamCreateWithFlags(&s2, cudaStreamNonBlocking);
        cudaFuncSetAttribute(k_pair, cudaFuncAttributeMaxDynamicSharedMemorySize, smemPair);
        cudaFuncSetAttribute(k_proj, cudaFuncAttributeMaxDynamicSharedMemorySize, smemAtom);
        cudaFuncSetAttribute(k_out,  cudaFuncAttributeMaxDynamicSharedMemorySize, smemOut);
        inited = true;
    }

    cudaEvent_t e0, e1;
    cudaEventCreateWithFlags(&e0, cudaEventDisableTiming);
    cudaEventCreateWithFlags(&e1, cudaEventDisableTiming);

    const int NT = N_PAIRS / 128;  // 12500

    // fork: side stream runs the k_gather prologue (independent of k_pair)
    cudaEventRecord(e0, 0);
    cudaStreamWaitEvent(s2, e0, 0);
    k_czero<<<(N_ATOMS + 255) / 256, 256, 0, s2>>>();
    k_bucket<<<(N_PAIRS + 255) / 256, 256, 0, s2>>>(pidx);
    k_proj<<<(N_ATOMS + 127) / 128, 256, smemAtom, s2>>>(emb, W_in);
    cudaEventRecord(e1, s2);

    // main chain: pair GEMMs (overlap with the fork)
    k_pair<<<148, 512, smemPair>>>(fij, cut, W_f1, b_f1, W_f2, b_f2, 0, NT / 2);
    k_pair<<<148, 512, smemPair>>>(fij, cut, W_f1, b_f1, W_f2, b_f2, NT / 2, NT - NT / 2);

    // join, then gather + output MLP
    cudaStreamWaitEvent(0, e1, 0);
    k_gather<<<(N_ATOMS * 32 + 255) / 256, 256>>>();
    k_out<<<(N_ATOMS + 127) / 128, 256, smemOut>>>(W_o1, b_o1, W_o2, b_o2, out);

    cudaEventDestroy(e0);
    cudaEventDestroy(e1);
}